// round 4
// baseline (speedup 1.0000x reference)
#include <cuda_runtime.h>
#include <cuda_fp16.h>
#include <cuda_bf16.h>

// Problem constants (from reference_code)
#define N_PATHS  10000000
#define MAX_LEN  3
#define N_NODES  100000
#define HIDDEN   128

// Nodes resident in shared memory (fp16, planar): 3 * 38000 * 2 = 228000 B
#define NS         38000
#define SMEM_HALFS (3 * NS + 8)          // +8 halves: zero slot + padding
#define SMEM_BYTES (SMEM_HALFS * 2)

// fp16 planar projection table: g_t16[l * N_NODES + node]
__device__ __half g_t16[3 * N_NODES];

// ---------------------------------------------------------------------------
// Kernel 1: proj[l][node] = dot(feature[node], W[l][0]) -> fp16 planar table.
// One warp per node; lane t covers dims [4t,4t+4) via float4.
// ---------------------------------------------------------------------------
__global__ void proj_kernel(const float* __restrict__ nf,
                            const float* __restrict__ W) {
    const int lane   = threadIdx.x & 31;
    const int warpIn = threadIdx.x >> 5;
    const int node   = blockIdx.x * (blockDim.x >> 5) + warpIn;
    if (node >= N_NODES) return;

    const float4 w0 = __ldg(((const float4*)W) + 0  + lane);
    const float4 w1 = __ldg(((const float4*)W) + 32 + lane);
    const float4 w2 = __ldg(((const float4*)W) + 64 + lane);

    const float4 f = __ldg(((const float4*)nf) + (size_t)node * 32 + lane);

    float s0 = f.x * w0.x + f.y * w0.y + f.z * w0.z + f.w * w0.w;
    float s1 = f.x * w1.x + f.y * w1.y + f.z * w1.z + f.w * w1.w;
    float s2 = f.x * w2.x + f.y * w2.y + f.z * w2.z + f.w * w2.w;

    #pragma unroll
    for (int o = 16; o > 0; o >>= 1) {
        s0 += __shfl_xor_sync(0xFFFFFFFFu, s0, o);
        s1 += __shfl_xor_sync(0xFFFFFFFFu, s1, o);
        s2 += __shfl_xor_sync(0xFFFFFFFFu, s2, o);
    }

    if (lane == 0) {
        g_t16[0 * N_NODES + node] = __float2half(s0);
        g_t16[1 * N_NODES + node] = __float2half(s1);
        g_t16[2 * N_NODES + node] = __float2half(s2);
    }
}

// ---------------------------------------------------------------------------
// Kernel 2: branchless hybrid gather + masked mean.
// Each access: one generic LD.U16 through a SEL-chain pointer:
//   p <  0   -> smem zero slot
//   p <  NS  -> smem plane   (s_tab + l*NS + p)
//   else     -> global plane (g_t16 + l*N_NODES + p)
// 2 quads (8 paths, 24 loads) per thread per iteration for MLP.
// ---------------------------------------------------------------------------
__global__ void __launch_bounds__(1024, 1)
gather_kernel(const int* __restrict__ paths, float* __restrict__ out) {
    extern __shared__ __half s_tab[];  // [3][NS] + zero slot

    const int tid = threadIdx.x;

    // Cooperative smem fill: per-plane copy (each plane 76000 B = 4750 x16B)
    #pragma unroll
    for (int l = 0; l < 3; l++) {
        const float4* src = (const float4*)(g_t16 + l * N_NODES);
        float4*       dst = (float4*)(s_tab + l * NS);
        for (int i = tid; i < (NS * 2) / 16; i += 1024)
            dst[i] = __ldg(src + i);
    }
    if (tid == 0) s_tab[3 * NS] = __float2half(0.0f);
    __syncthreads();

    const __half* zslot = s_tab + 3 * NS;

    const long long NPAIR = N_PATHS / 8;  // pairs of quads (8 paths each)
    const long long b0 = (long long)blockIdx.x * NPAIR / gridDim.x;
    const long long b1 = (long long)(blockIdx.x + 1) * NPAIR / gridDim.x;

    for (long long pr = b0 + tid; pr < b1; pr += 1024) {
        // 8 paths = 24 int32 indices = 6 x int4 (coalesced, 96 B/thread)
        const int4* p4 = ((const int4*)paths) + pr * 6;
        int4 u0 = __ldg(p4 + 0);
        int4 u1 = __ldg(p4 + 1);
        int4 u2 = __ldg(p4 + 2);
        int4 u3 = __ldg(p4 + 3);
        int4 u4 = __ldg(p4 + 4);
        int4 u5 = __ldg(p4 + 5);

        int idx[24] = { u0.x, u0.y, u0.z, u0.w,  u1.x, u1.y, u1.z, u1.w,
                        u2.x, u2.y, u2.z, u2.w,  u3.x, u3.y, u3.z, u3.w,
                        u4.x, u4.y, u4.z, u4.w,  u5.x, u5.y, u5.z, u5.w };

        // Branchless pointer select + 24 independent generic loads
        __half h[24];
        #pragma unroll
        for (int j = 0; j < 24; j++) {
            const int p = idx[j];
            const int l = j - (j / 3) * 3;   // j % 3
            const __half* ptr =
                (p >= 0) ? ((p < NS) ? (s_tab + l * NS + p)
                                     : (g_t16 + l * N_NODES + p))
                         : zslot;
            h[j] = *ptr;
        }

        float4 ra, rb;
        float* r = (float*)&ra;   // r[0..3] -> ra, r[4..7] -> rb via second ptr
        float* r2 = (float*)&rb;

        #pragma unroll
        for (int k = 0; k < 8; k++) {
            const int j = k * 3;
            float s = __half2float(h[j]) + __half2float(h[j + 1]) +
                      __half2float(h[j + 2]);
            int cnt = (idx[j] >= 0) + (idx[j + 1] >= 0) + (idx[j + 2] >= 0);
            float v = s / (float)(cnt > 0 ? cnt : 1);
            if (k < 4) r[k] = v; else r2[k - 4] = v;
        }

        float4* o4 = ((float4*)out) + pr * 2;
        o4[0] = ra;
        o4[1] = rb;
    }
}

// ---------------------------------------------------------------------------
// Launch. Inputs identified by element count:
//   30,000,000 -> paths (int32 [10M,3]); 12,800,000 -> node_feature; 384 -> W
// ---------------------------------------------------------------------------
extern "C" void kernel_launch(void* const* d_in, const int* in_sizes, int n_in,
                              void* d_out, int out_size) {
    const void*  paths_raw = nullptr;
    const float* nf        = nullptr;
    const float* W         = nullptr;

    for (int i = 0; i < n_in; i++) {
        if      (in_sizes[i] == N_PATHS * MAX_LEN)  paths_raw = d_in[i];
        else if (in_sizes[i] == N_NODES * HIDDEN)   nf        = (const float*)d_in[i];
        else if (in_sizes[i] == MAX_LEN * HIDDEN)   W         = (const float*)d_in[i];
    }

    float* out = (float*)d_out;

    static bool attr_done = false;
    if (!attr_done) {
        cudaFuncSetAttribute(gather_kernel,
                             cudaFuncAttributeMaxDynamicSharedMemorySize,
                             SMEM_BYTES);
        attr_done = true;
    }

    // proj: one warp per node
    {
        const int threads = 256;
        const int warpsPerBlock = threads / 32;
        const int blocks = (N_NODES + warpsPerBlock - 1) / warpsPerBlock;
        proj_kernel<<<blocks, threads>>>(nf, W);
    }

    // gather: 1 CTA per SM, 1024 threads
    gather_kernel<<<148, 1024, SMEM_BYTES>>>((const int*)paths_raw, out);
}

// round 5
// speedup vs baseline: 1.1606x; 1.1606x over previous
#include <cuda_runtime.h>
#include <cuda_fp16.h>
#include <cuda_bf16.h>

// Problem constants (from reference_code)
#define N_PATHS  10000000
#define MAX_LEN  3
#define N_NODES  100000
#define HIDDEN   128

// Nodes resident in shared memory (fp16, planar): 3 * 38000 * 2 = 228000 B
#define NS         38000
#define SMEM_BYTES (3 * NS * 2 + 16)

// fp16 planar projection table: g_t16[l * N_NODES + node]
__device__ __half g_t16[3 * N_NODES];

// ---------------------------------------------------------------------------
// Kernel 1: proj[l][node] = dot(feature[node], W[l][0]) -> fp16 planar table.
// ---------------------------------------------------------------------------
__global__ void proj_kernel(const float* __restrict__ nf,
                            const float* __restrict__ W) {
    const int lane   = threadIdx.x & 31;
    const int warpIn = threadIdx.x >> 5;
    const int node   = blockIdx.x * (blockDim.x >> 5) + warpIn;
    if (node >= N_NODES) return;

    const float4 w0 = __ldg(((const float4*)W) + 0  + lane);
    const float4 w1 = __ldg(((const float4*)W) + 32 + lane);
    const float4 w2 = __ldg(((const float4*)W) + 64 + lane);

    const float4 f = __ldg(((const float4*)nf) + (size_t)node * 32 + lane);

    float s0 = f.x * w0.x + f.y * w0.y + f.z * w0.z + f.w * w0.w;
    float s1 = f.x * w1.x + f.y * w1.y + f.z * w1.z + f.w * w1.w;
    float s2 = f.x * w2.x + f.y * w2.y + f.z * w2.z + f.w * w2.w;

    #pragma unroll
    for (int o = 16; o > 0; o >>= 1) {
        s0 += __shfl_xor_sync(0xFFFFFFFFu, s0, o);
        s1 += __shfl_xor_sync(0xFFFFFFFFu, s1, o);
        s2 += __shfl_xor_sync(0xFFFFFFFFu, s2, o);
    }

    if (lane == 0) {
        g_t16[0 * N_NODES + node] = __float2half(s0);
        g_t16[1 * N_NODES + node] = __float2half(s1);
        g_t16[2 * N_NODES + node] = __float2half(s2);
    }
}

// Predicated global fp16 load: issues LDG only when p >= NS. No branches.
__device__ __forceinline__ unsigned short ldg_if_big(const __half* addr, int p) {
    unsigned short v = 0;
    asm volatile(
        "{ .reg .pred q;\n\t"
        "  setp.ge.s32 q, %1, %3;\n\t"
        "  @q ld.global.nc.u16 %0, [%2];\n\t"
        "}"
        : "+h"(v) : "r"(p), "l"(addr), "n"(NS));
    return v;
}

// ---------------------------------------------------------------------------
// Kernel 2: branchless hybrid gather + masked mean.
//  - every access: clamped LDS (smem crossbar) + predicated LDG (p >= NS)
//  - SEL combine, zero-mask for p < 0, reciprocal-by-select
// One quad (4 paths, 12 accesses) per thread per iteration.
// ---------------------------------------------------------------------------
__global__ void __launch_bounds__(1024, 1)
gather_kernel(const int* __restrict__ paths, float* __restrict__ out) {
    extern __shared__ __half s_tab[];  // [3][NS]

    const int tid = threadIdx.x;

    // Cooperative smem fill (3 planes x 76000 B)
    #pragma unroll
    for (int l = 0; l < 3; l++) {
        const float4* src = (const float4*)(g_t16 + l * N_NODES);
        float4*       dst = (float4*)(s_tab + l * NS);
        for (int i = tid; i < (NS * 2) / 16; i += 1024)
            dst[i] = __ldg(src + i);
    }
    __syncthreads();

    const long long QT = N_PATHS / 4;  // 2.5M quads
    const long long q0 = (long long)blockIdx.x * QT / gridDim.x;
    const long long q1 = (long long)(blockIdx.x + 1) * QT / gridDim.x;

    for (long long q = q0 + tid; q < q1; q += 1024) {
        const int4* p4 = ((const int4*)paths) + q * 3;
        int4 v0 = __ldg(p4 + 0);
        int4 v1 = __ldg(p4 + 1);
        int4 v2 = __ldg(p4 + 2);

        int idx[12] = { v0.x, v0.y, v0.z, v0.w,
                        v1.x, v1.y, v1.z, v1.w,
                        v2.x, v2.y, v2.z, v2.w };

        // Phase 1: 12 predicated LDGs, front-batched (addresses die at issue)
        unsigned short gv[12];
        #pragma unroll
        for (int j = 0; j < 12; j++) {
            const int l = j - (j / 3) * 3;  // j % 3
            gv[j] = ldg_if_big(g_t16 + l * N_NODES + idx[j], idx[j]);
        }

        // Phase 2: 12 unconditional clamped LDS (parallel pipe)
        __half sv[12];
        #pragma unroll
        for (int j = 0; j < 12; j++) {
            const int l = j - (j / 3) * 3;
            unsigned int up = (unsigned int)idx[j];
            up = (up < NS) ? up : 0u;       // clamps negatives & >= NS
            sv[j] = s_tab[l * NS + up];
        }

        // Phase 3: branchless combine
        float4 res;
        float* r = (float*)&res;
        #pragma unroll
        for (int k = 0; k < 4; k++) {
            float s = 0.0f;
            int   cnt = 0;
            #pragma unroll
            for (int l = 0; l < 3; l++) {
                const int j = k * 3 + l;
                const int p = idx[j];
                __half hv = ((unsigned int)p < NS)
                              ? sv[j]
                              : __ushort_as_half(gv[j]);
                float  f  = (p >= 0) ? __half2float(hv) : 0.0f;
                s   += f;
                cnt += (p >= 0);
            }
            float inv = (cnt == 3) ? (1.0f / 3.0f)
                                   : ((cnt == 2) ? 0.5f : 1.0f);
            r[k] = s * inv;
        }

        ((float4*)out)[q] = res;
    }
}

// ---------------------------------------------------------------------------
// Launch. Inputs identified by element count:
//   30,000,000 -> paths (int32 [10M,3]); 12,800,000 -> node_feature; 384 -> W
// ---------------------------------------------------------------------------
extern "C" void kernel_launch(void* const* d_in, const int* in_sizes, int n_in,
                              void* d_out, int out_size) {
    const void*  paths_raw = nullptr;
    const float* nf        = nullptr;
    const float* W         = nullptr;

    for (int i = 0; i < n_in; i++) {
        if      (in_sizes[i] == N_PATHS * MAX_LEN)  paths_raw = d_in[i];
        else if (in_sizes[i] == N_NODES * HIDDEN)   nf        = (const float*)d_in[i];
        else if (in_sizes[i] == MAX_LEN * HIDDEN)   W         = (const float*)d_in[i];
    }

    float* out = (float*)d_out;

    static bool attr_done = false;
    if (!attr_done) {
        cudaFuncSetAttribute(gather_kernel,
                             cudaFuncAttributeMaxDynamicSharedMemorySize,
                             SMEM_BYTES);
        attr_done = true;
    }

    // proj: one warp per node
    {
        const int threads = 256;
        const int warpsPerBlock = threads / 32;
        const int blocks = (N_NODES + warpsPerBlock - 1) / warpsPerBlock;
        proj_kernel<<<blocks, threads>>>(nf, W);
    }

    // gather: 1 CTA per SM, 1024 threads, 228 KB smem
    gather_kernel<<<148, 1024, SMEM_BYTES>>>((const int*)paths_raw, out);
}